// round 3
// baseline (speedup 1.0000x reference)
#include <cuda_runtime.h>

#define DD 8
#define BB 4096
#define VV 1024
#define K_SEL 102
#define THREADS 256
#define WARPS 8

__device__ int g_samples[DD * BB];

__device__ __forceinline__ unsigned fkey(float f) {
    unsigned b = __float_as_uint(f);
    return (b & 0x80000000u) ? ~b : (b | 0x80000000u);
}
__device__ __forceinline__ float keyf(unsigned k) {
    unsigned b = (k & 0x80000000u) ? (k & 0x7FFFFFFFu) : ~k;
    return __uint_as_float(b);
}
// padded histogram index: bins b and b+8 land in different banks
__device__ __forceinline__ int H(int b) { return b + (b >> 3); }

__global__ __launch_bounds__(THREADS, 4)
void decode_kernel(const float* __restrict__ logits,
                   const float* __restrict__ uin,
                   const int* __restrict__ curv,
                   float* __restrict__ out_probs,
                   int write_probs)
{
    const int tid  = threadIdx.x;
    const int lane = tid & 31;
    const int wid  = tid >> 5;
    const int r    = blockIdx.x * WARPS + wid;     // one warp per row
    const size_t base = (size_t)r * VV;
    const int cur  = curv[r];
    const unsigned FULL = 0xffffffffu;

    __shared__ int hist[WARPS][288];               // 256 bins, 9/8 padded

    // ---- load logits once -> masked monotone keys (32 per lane) ----
    unsigned keys[32];
#pragma unroll
    for (int i = 0; i < 8; ++i) {
        float4 lv = ((const float4*)(logits + base))[i * 32 + lane];
        float v[4] = {lv.x, lv.y, lv.z, lv.w};
#pragma unroll
        for (int c = 0; c < 4; ++c) {
            int idx = (i * 32 + lane) * 4 + c;
            if (idx < cur || idx == 0) v[c] = __int_as_float(0xff800000);
            keys[i * 4 + c] = fkey(v[c]);
        }
    }

    // ---- exact k-th largest: 4x8-bit radix select, warp-local ----
    unsigned prefix = 0u, pmask = 0u;
    int krem = K_SEL;
#pragma unroll
    for (int pass = 0; pass < 4; ++pass) {
        const int shift = 24 - 8 * pass;
#pragma unroll
        for (int k = 0; k < 8; ++k) hist[wid][H(k * 32 + lane)] = 0;
        __syncwarp();
#pragma unroll
        for (int e = 0; e < 32; ++e)
            if ((keys[e] & pmask) == prefix)
                atomicAdd(&hist[wid][H((keys[e] >> shift) & 0xFF)], 1);
        __syncwarp();
        // lane owns bins [lane*8, lane*8+8); suffix scan from high bins
        int cnt[8], lsum = 0;
#pragma unroll
        for (int k = 0; k < 8; ++k) { cnt[k] = hist[wid][H(lane * 8 + k)]; lsum += cnt[k]; }
        int suf = lsum;                            // inclusive suffix over lanes
#pragma unroll
        for (int off = 1; off < 32; off <<= 1) {
            int y = __shfl_down_sync(FULL, suf, off);
            if (lane + off < 32) suf += y;
        }
        int run = suf - lsum;                      // sum over lanes > lane
        int sel = -1, nk = 0;
#pragma unroll
        for (int k = 7; k >= 0; --k) {
            int c = cnt[k];
            if (sel < 0 && run < krem && run + c >= krem) { sel = lane * 8 + k; nk = krem - run; }
            run += c;
        }
        unsigned bal = __ballot_sync(FULL, sel >= 0);
        int src = __ffs(bal) - 1;
        sel = __shfl_sync(FULL, sel, src);
        nk  = __shfl_sync(FULL, nk,  src);
        prefix |= (unsigned)sel << shift;
        pmask  |= 0xFFu << shift;
        krem = nk;
        __syncwarp();
    }
    // prefix == monotone key of the exact k-th largest value; kept := key >= prefix

    // ---- row max (exact; butterfly so all lanes hold it) ----
    unsigned mk = 0u;
#pragma unroll
    for (int e = 0; e < 32; ++e) mk = max(mk, keys[e]);
#pragma unroll
    for (int off = 16; off >= 1; off >>= 1)
        mk = max(mk, __shfl_xor_sync(FULL, mk, off));
    const float m = keyf(mk);

    // ---- sum exp over kept (butterfly sum: identical value in all lanes) ----
    float s = 0.f;
#pragma unroll
    for (int e = 0; e < 32; ++e)
        if (keys[e] >= prefix) s += expf(keyf(keys[e]) - m);
#pragma unroll
    for (int off = 16; off >= 1; off >>= 1)
        s += __shfl_xor_sync(FULL, s, off);
    const float logZ = m + logf(s);

    // ---- probs out + Gumbel argmax; u loaded ONLY for kept positions ----
    unsigned long long best = 0ull;
#pragma unroll
    for (int i = 0; i < 8; ++i) {
        float p[4];
#pragma unroll
        for (int c = 0; c < 4; ++c) {
            unsigned key = keys[i * 4 + c];
            p[c] = 0.f;
            if (key >= prefix) {
                float lp = keyf(key) - logZ;
                p[c] = expf(lp);
                int idx = (i * 32 + lane) * 4 + c;
                float u = __ldg(uin + base + idx);
                float g  = -logf(-logf(u + 1e-20f) + 1e-20f);
                float sc = lp + g;                 // same expression as reference
                unsigned long long k64 =
                    ((unsigned long long)fkey(sc) << 32) |
                    (unsigned long long)(0xFFFFFFFFu - (unsigned)idx);
                if (k64 > best) best = k64;
            }
        }
        if (write_probs)
            ((float4*)(out_probs + base))[i * 32 + lane] =
                make_float4(p[0], p[1], p[2], p[3]);
    }
#pragma unroll
    for (int off = 16; off >= 1; off >>= 1) {
        unsigned long long o = __shfl_xor_sync(FULL, best, off);
        if (o > best) best = o;
    }
    if (lane == 0)
        g_samples[r] = (int)(0xFFFFFFFFu - (unsigned)(best & 0xFFFFFFFFull));
}

__global__ void tokens_kernel(float* __restrict__ out_tok)
{
    int i = blockIdx.x * blockDim.x + threadIdx.x;   // i in [0, B*D)
    if (i >= BB * DD) return;
    int b = i / DD, d = i % DD;
    int s0 = g_samples[b];                // field 0 sample for stream b
    int sd = g_samples[d * BB + b];
    int val = (d == 0 || s0 == 1) ? sd : 0;    // NOTE_TYPE == 1
    out_tok[i] = (float)val;                   // tokens.T flattened [B,D]
}

extern "C" void kernel_launch(void* const* d_in, const int* in_sizes, int n_in,
                              void* d_out, int out_size)
{
    const float* logits = (const float*)d_in[0];
    const float* uin    = (const float*)d_in[1];
    const int*   curv   = (const int*)d_in[2];
    float* out = (float*)d_out;

    const size_t probsN = (size_t)DD * BB * VV;
    const size_t tokN   = (size_t)BB * DD;

    float* out_tok = nullptr;
    float* out_probs = nullptr;
    if ((size_t)out_size >= probsN + tokN) {        // concat: tokens.T then probs
        out_tok = out; out_probs = out + tokN;
    } else if ((size_t)out_size >= probsN) {        // probs only
        out_probs = out;
    } else {                                        // tokens only
        out_tok = out;
    }

    decode_kernel<<<(DD * BB) / WARPS, THREADS>>>(logits, uin, curv,
                                                  out_probs ? out_probs : out,
                                                  out_probs != nullptr ? 1 : 0);
    if (out_tok)
        tokens_kernel<<<(BB * DD + 255) / 256, 256>>>(out_tok);
}

// round 4
// speedup vs baseline: 1.2814x; 1.2814x over previous
#include <cuda_runtime.h>

#define DD 8
#define BB 4096
#define VV 1024
#define K_SEL 102
#define THREADS 256

__device__ int g_samples[DD * BB];

__device__ __forceinline__ unsigned fkey(float f) {
    unsigned b = __float_as_uint(f);
    return (b & 0x80000000u) ? ~b : (b | 0x80000000u);
}
__device__ __forceinline__ float keyf(unsigned k) {
    unsigned b = (k & 0x80000000u) ? (k & 0x7FFFFFFFu) : ~k;
    return __uint_as_float(b);
}

__global__ __launch_bounds__(THREADS)
void decode_kernel(const float* __restrict__ logits,
                   const float* __restrict__ uin,
                   const int* __restrict__ curv,
                   float* __restrict__ out_probs,
                   int write_probs)
{
    const int r    = blockIdx.x;            // r = d*B + b
    const int tid  = threadIdx.x;
    const int lane = tid & 31;
    const int wid  = tid >> 5;
    const float NEG = __int_as_float(0xff800000); // -inf
    const size_t base = (size_t)r * VV;
    const int cur = curv[r];
    const unsigned FULL = 0xffffffffu;

    __shared__ int sh_hist[256];
    __shared__ int sh_wsum[8];
    __shared__ unsigned sh_sel;
    __shared__ int sh_krem;
    __shared__ unsigned sh_maxkey;
    __shared__ unsigned long long sh_best;
    __shared__ float sh_red[8];
    __shared__ float sh_logZ;

    if (tid == 0) { sh_maxkey = 0u; sh_best = 0ull; }

    // ---- load logits once (vectorized); u loaded lazily later ----
    float4 lv = ((const float4*)(logits + base))[tid];
    float vals[4] = {lv.x, lv.y, lv.z, lv.w};
    const int vbase = tid * 4;

    unsigned keys[4];
#pragma unroll
    for (int j = 0; j < 4; ++j) {
        int v = vbase + j;
        if (v < cur || v == 0) vals[j] = NEG;
        keys[j] = fkey(vals[j]);
    }

    // row max folded in front of the radix passes (shares their barriers)
    unsigned lmax = max(max(keys[0], keys[1]), max(keys[2], keys[3]));
    atomicMax(&sh_maxkey, lmax);

    // ---- exact k-th largest via 4x8-bit radix select ----
    unsigned prefix = 0u, pmask = 0u;
    int krem = K_SEL;
#pragma unroll
    for (int pass = 0; pass < 4; ++pass) {
        const int shift = 24 - 8 * pass;
        sh_hist[tid] = 0;
        __syncthreads();
#pragma unroll
        for (int j = 0; j < 4; ++j)
            if ((keys[j] & pmask) == prefix)
                atomicAdd(&sh_hist[(keys[j] >> shift) & 0xFFu], 1);
        __syncthreads();
        int cnt = sh_hist[tid];
        int x = cnt;                       // warp suffix scan (inclusive)
#pragma unroll
        for (int off = 1; off < 32; off <<= 1) {
            int y = __shfl_down_sync(FULL, x, off);
            if (lane + off < 32) x += y;
        }
        if (lane == 0) sh_wsum[wid] = x;   // warp total
        __syncthreads();
        int tail = 0;
#pragma unroll
        for (int w = 1; w < 8; ++w)
            if (w > wid) tail += sh_wsum[w];
        int suffix = x + tail;             // count of keys in buckets >= tid (within prefix)
        if (suffix >= krem && (suffix - cnt) < krem) {
            sh_sel  = (unsigned)tid;
            sh_krem = krem - (suffix - cnt);
        }
        __syncthreads();
        prefix |= sh_sel << shift;
        pmask  |= 0xFFu << shift;
        krem    = sh_krem;
    }
    const float kth = keyf(prefix);
    const float m   = keyf(sh_maxkey);     // ready (barriers above fenced it)

    // ---- sum(exp(x - m)) over kept, fixed-order tree (deterministic) ----
    float s = 0.f;
#pragma unroll
    for (int j = 0; j < 4; ++j)
        if (vals[j] >= kth) s += __expf(vals[j] - m);
#pragma unroll
    for (int off = 16; off >= 1; off >>= 1)
        s += __shfl_down_sync(FULL, s, off);
    if (lane == 0) sh_red[wid] = s;
    __syncthreads();
    if (tid == 0) {
        float t = 0.f;
#pragma unroll
        for (int w = 0; w < 8; ++w) t += sh_red[w];
        sh_logZ = m + __logf(t);
    }
    __syncthreads();
    const float logZ = sh_logZ;

    // ---- probs out + Gumbel argmax; u loaded ONLY for kept positions ----
    float p[4];
    bool kept[4];
#pragma unroll
    for (int j = 0; j < 4; ++j) {
        kept[j] = (vals[j] >= kth);
        p[j] = kept[j] ? __expf(vals[j] - logZ) : 0.f;
    }

    unsigned long long best = 0ull;
    bool anyk = kept[0] | kept[1] | kept[2] | kept[3];
    if (__ballot_sync(FULL, anyk)) {       // whole warp skips when nothing kept
#pragma unroll
        for (int j = 0; j < 4; ++j) {
            if (kept[j]) {
                int idx = vbase + j;
                float u  = __ldg(uin + base + idx);
                float g  = -__logf(-__logf(u + 1e-20f) + 1e-20f);
                float sc = (vals[j] - logZ) + g;   // same expression as reference
                unsigned long long k64 =
                    ((unsigned long long)fkey(sc) << 32) |
                    (unsigned long long)(0xFFFFFFFFu - (unsigned)idx);
                if (k64 > best) best = k64;
            }
        }
    }
    if (best) atomicMax(&sh_best, best);
    if (write_probs)
        ((float4*)(out_probs + base))[tid] = make_float4(p[0], p[1], p[2], p[3]);
    __syncthreads();
    if (tid == 0)
        g_samples[r] = (int)(0xFFFFFFFFu - (unsigned)(sh_best & 0xFFFFFFFFull));
}

__global__ void tokens_kernel(float* __restrict__ out_tok)
{
    int i = blockIdx.x * blockDim.x + threadIdx.x;   // i in [0, B*D)
    if (i >= BB * DD) return;
    int b = i / DD, d = i % DD;
    int s0 = g_samples[b];                // field 0 sample for stream b
    int sd = g_samples[d * BB + b];
    int val = (d == 0 || s0 == 1) ? sd : 0;    // NOTE_TYPE == 1
    out_tok[i] = (float)val;                   // tokens.T flattened [B,D]
}

extern "C" void kernel_launch(void* const* d_in, const int* in_sizes, int n_in,
                              void* d_out, int out_size)
{
    const float* logits = (const float*)d_in[0];
    const float* uin    = (const float*)d_in[1];
    const int*   curv   = (const int*)d_in[2];
    float* out = (float*)d_out;

    const size_t probsN = (size_t)DD * BB * VV;
    const size_t tokN   = (size_t)BB * DD;

    float* out_tok = nullptr;
    float* out_probs = nullptr;
    if ((size_t)out_size >= probsN + tokN) {        // concat: tokens.T then probs
        out_tok = out; out_probs = out + tokN;
    } else if ((size_t)out_size >= probsN) {        // probs only
        out_probs = out;
    } else {                                        // tokens only
        out_tok = out;
    }

    decode_kernel<<<DD * BB, THREADS>>>(logits, uin, curv,
                                        out_probs ? out_probs : out,
                                        out_probs != nullptr ? 1 : 0);
    if (out_tok)
        tokens_kernel<<<(BB * DD + 255) / 256, 256>>>(out_tok);
}

// round 5
// speedup vs baseline: 1.3872x; 1.0825x over previous
#include <cuda_runtime.h>

#define DD 8
#define BB 4096
#define VV 1024
#define K_SEL 102
#define THREADS 256

__device__ int g_samples[DD * BB];

__device__ __forceinline__ unsigned fkey(float f) {
    unsigned b = __float_as_uint(f);
    return (b & 0x80000000u) ? ~b : (b | 0x80000000u);
}
__device__ __forceinline__ float keyf(unsigned k) {
    unsigned b = (k & 0x80000000u) ? (k & 0x7FFFFFFFu) : ~k;
    return __uint_as_float(b);
}

__global__ __launch_bounds__(THREADS)
void decode_kernel(const float* __restrict__ logits,
                   const float* __restrict__ uin,
                   const int* __restrict__ curv,
                   float* __restrict__ out_probs,
                   int write_probs)
{
    const int r    = blockIdx.x;            // r = d*B + b
    const int tid  = threadIdx.x;
    const int lane = tid & 31;
    const int wid  = tid >> 5;
    const float NEG = __int_as_float(0xff800000); // -inf
    const size_t base = (size_t)r * VV;
    const int cur = curv[r];
    const unsigned FULL = 0xffffffffu;

    __shared__ int sh_hist[256];
    __shared__ int sh_wsum[8];
    __shared__ unsigned sh_sel;
    __shared__ int sh_krem;
    __shared__ int sh_cnt;
    __shared__ unsigned sh_maxkey;
    __shared__ unsigned long long sh_best;
    __shared__ float sh_red[8];
    __shared__ float sh_logZ;

    if (tid < 256) sh_hist[tid] = 0;
    if (tid == 0) { sh_maxkey = 0u; sh_best = 0ull; }

    // ---- load logits once (vectorized); u loaded lazily later ----
    float4 lv = ((const float4*)(logits + base))[tid];
    float vals[4] = {lv.x, lv.y, lv.z, lv.w};
    const int vbase = tid * 4;

    unsigned keys[4];
#pragma unroll
    for (int j = 0; j < 4; ++j) {
        int v = vbase + j;
        if (v < cur || v == 0) vals[j] = NEG;
        keys[j] = fkey(vals[j]);
    }

    // ---- row max: butterfly in-warp, then 1 atomic per warp ----
    unsigned lmax = max(max(keys[0], keys[1]), max(keys[2], keys[3]));
#pragma unroll
    for (int off = 16; off >= 1; off >>= 1)
        lmax = max(lmax, __shfl_xor_sync(FULL, lmax, off));
    if (lane == 0) atomicMax(&sh_maxkey, lmax);

    // ---- exact k-th threshold via radix select with early exact break ----
    unsigned prefix = 0u, pmask = 0u;
    int krem = K_SEL;
    for (int pass = 0; pass < 4; ++pass) {
        const int shift = 24 - 8 * pass;
        __syncthreads();                   // hist zeroed & prefix published
#pragma unroll
        for (int j = 0; j < 4; ++j)
            if ((keys[j] & pmask) == prefix)
                atomicAdd(&sh_hist[(keys[j] >> shift) & 0xFFu], 1);
        __syncthreads();
        int cnt = sh_hist[tid];
        sh_hist[tid] = 0;                  // self-bin reset for next pass
        int x = cnt;                       // warp suffix scan (inclusive)
#pragma unroll
        for (int off = 1; off < 32; off <<= 1) {
            int y = __shfl_down_sync(FULL, x, off);
            if (lane + off < 32) x += y;
        }
        if (lane == 0) sh_wsum[wid] = x;   // warp total
        __syncthreads();
        int tail = 0;
#pragma unroll
        for (int w = 1; w < 8; ++w)
            if (w > wid) tail += sh_wsum[w];
        int suffix = x + tail;             // keys in buckets >= tid (within prefix)
        if (suffix >= krem && (suffix - cnt) < krem) {
            sh_sel  = (unsigned)tid;
            sh_krem = krem - (suffix - cnt);
            sh_cnt  = cnt;
        }
        __syncthreads();
        prefix |= sh_sel << shift;
        pmask  |= 0xFFu << shift;
        krem    = sh_krem;
        // exact early exit: whole selected bucket is kept
        if (sh_cnt == krem) break;
    }
    // kept := key >= prefix  (exact: either full 32-bit kth key, or bucket
    // floor when the entire boundary bucket is kept)
    const float m = keyf(sh_maxkey);       // fenced by the barriers above

    // ---- sum(exp(x - m)) over kept, fixed-order tree (deterministic) ----
    float s = 0.f;
#pragma unroll
    for (int j = 0; j < 4; ++j)
        if (keys[j] >= prefix) s += __expf(vals[j] - m);
#pragma unroll
    for (int off = 16; off >= 1; off >>= 1)
        s += __shfl_down_sync(FULL, s, off);
    if (lane == 0) sh_red[wid] = s;
    __syncthreads();
    if (tid == 0) {
        float t = 0.f;
#pragma unroll
        for (int w = 0; w < 8; ++w) t += sh_red[w];
        sh_logZ = m + __logf(t);
    }
    __syncthreads();
    const float logZ = sh_logZ;

    // ---- probs out + Gumbel argmax; u loaded ONLY for kept positions ----
    float p[4];
    bool kept[4];
#pragma unroll
    for (int j = 0; j < 4; ++j) {
        kept[j] = (keys[j] >= prefix);
        p[j] = kept[j] ? __expf(vals[j] - logZ) : 0.f;
    }

    unsigned long long best = 0ull;
    bool anyk = kept[0] | kept[1] | kept[2] | kept[3];
    if (__ballot_sync(FULL, anyk)) {       // whole warp skips when nothing kept
#pragma unroll
        for (int j = 0; j < 4; ++j) {
            if (kept[j]) {
                int idx = vbase + j;
                float u  = __ldg(uin + base + idx);
                float g  = -__logf(-__logf(u + 1e-20f) + 1e-20f);
                float sc = (vals[j] - logZ) + g;   // same expression as reference
                unsigned long long k64 =
                    ((unsigned long long)fkey(sc) << 32) |
                    (unsigned long long)(0xFFFFFFFFu - (unsigned)idx);
                if (k64 > best) best = k64;
            }
        }
    }
    if (best) atomicMax(&sh_best, best);
    if (write_probs)
        ((float4*)(out_probs + base))[tid] = make_float4(p[0], p[1], p[2], p[3]);
    __syncthreads();
    if (tid == 0)
        g_samples[r] = (int)(0xFFFFFFFFu - (unsigned)(sh_best & 0xFFFFFFFFull));
}

__global__ void tokens_kernel(float* __restrict__ out_tok)
{
    int i = blockIdx.x * blockDim.x + threadIdx.x;   // i in [0, B*D)
    if (i >= BB * DD) return;
    int b = i / DD, d = i % DD;
    int s0 = g_samples[b];                // field 0 sample for stream b
    int sd = g_samples[d * BB + b];
    int val = (d == 0 || s0 == 1) ? sd : 0;    // NOTE_TYPE == 1
    out_tok[i] = (float)val;                   // tokens.T flattened [B,D]
}

extern "C" void kernel_launch(void* const* d_in, const int* in_sizes, int n_in,
                              void* d_out, int out_size)
{
    const float* logits = (const float*)d_in[0];
    const float* uin    = (const float*)d_in[1];
    const int*   curv   = (const int*)d_in[2];
    float* out = (float*)d_out;

    const size_t probsN = (size_t)DD * BB * VV;
    const size_t tokN   = (size_t)BB * DD;

    float* out_tok = nullptr;
    float* out_probs = nullptr;
    if ((size_t)out_size >= probsN + tokN) {        // concat: tokens.T then probs
        out_tok = out; out_probs = out + tokN;
    } else if ((size_t)out_size >= probsN) {        // probs only
        out_probs = out;
    } else {                                        // tokens only
        out_tok = out;
    }

    decode_kernel<<<DD * BB, THREADS>>>(logits, uin, curv,
                                        out_probs ? out_probs : out,
                                        out_probs != nullptr ? 1 : 0);
    if (out_tok)
        tokens_kernel<<<(BB * DD + 255) / 256, 256>>>(out_tok);
}